// round 12
// baseline (speedup 1.0000x reference)
#include <cuda_runtime.h>
#include <math.h>

#define Sq  2048
#define Dd  512
#define Hh  8
#define DHh 64
#define CWw 128
#define NSPLIT 4
#define KSPL (Dd / NSPLIT)    // 128

// ---------------- scratch (device globals) -------------------------------------
__device__ float g_cur[Sq * Dd];
__device__ float g_q[Sq * DHh];
__device__ float g_k[Sq * DHh];
__device__ float g_v[Sq * DHh];
__device__ float g_y[Sq * Dd];
__device__ float g_part[3][NSPLIT][Sq * DHh];
__device__ float g_pm[2][Sq];            // partial softmax max
__device__ float g_ps[2][Sq];            // partial softmax sum(exp)
__device__ float g_pv[2][Sq * DHh];      // partial sum(exp * V)
__device__ float g_s1[2][Sq];            // per-token partial sum(y)
__device__ float g_s2[2][Sq];            // per-token partial sum(y^2)

// ---------------- init: cur = x -------------------------------------------------
__global__ void init_kernel(const float4* __restrict__ x) {
    int i = blockIdx.x * blockDim.x + threadIdx.x;
    ((float4*)g_cur)[i] = x[i];
}

// ---------------- qkv split-K partial GEMM (proven, at fp32 floor) --------------
__global__ __launch_bounds__(128) void qkv_partial(const float* __restrict__ Wq,
                                                   const float* __restrict__ Wk,
                                                   const float* __restrict__ Wvd, int h)
{
    __shared__ float Xs[32][36];
    __shared__ float Ws[32][68];

    const int sel = blockIdx.y;
    const int sp  = blockIdx.z;
    const float* B = (sel == 0 ? Wq : sel == 1 ? Wk : Wvd) + (size_t)h * DHh * Dd;
    float* C = &g_part[sel][sp][0];
    const int m0 = blockIdx.x * 32;
    const int kb = sp * KSPL;

    const int t  = threadIdx.x;
    const int tx = t & 15;
    const int ty = t >> 4;

    float acc[4][4] = {};

    for (int k0 = kb; k0 < kb + KSPL; k0 += 32) {
        #pragma unroll
        for (int r = 0; r < 2; r++) {
            int f = t + r * 128;
            int m = f >> 3, kv = f & 7;
            float4 va = *(const float4*)&g_cur[(size_t)(m0 + m) * Dd + k0 + kv * 4];
            Xs[kv * 4 + 0][m] = va.x;
            Xs[kv * 4 + 1][m] = va.y;
            Xs[kv * 4 + 2][m] = va.z;
            Xs[kv * 4 + 3][m] = va.w;
        }
        #pragma unroll
        for (int r = 0; r < 4; r++) {
            int f = t + r * 128;
            int n = f >> 3, kv = f & 7;
            float4 vb = *(const float4*)&B[(size_t)n * Dd + k0 + kv * 4];
            Ws[kv * 4 + 0][n] = vb.x;
            Ws[kv * 4 + 1][n] = vb.y;
            Ws[kv * 4 + 2][n] = vb.z;
            Ws[kv * 4 + 3][n] = vb.w;
        }
        __syncthreads();

        #pragma unroll
        for (int k = 0; k < 32; k++) {
            float4 a4 = *(const float4*)&Xs[k][ty * 4];
            float4 b4 = *(const float4*)&Ws[k][tx * 4];
            float a[4] = {a4.x, a4.y, a4.z, a4.w};
            float b[4] = {b4.x, b4.y, b4.z, b4.w};
            #pragma unroll
            for (int i = 0; i < 4; i++)
                #pragma unroll
                for (int j = 0; j < 4; j++)
                    acc[i][j] = fmaf(a[i], b[j], acc[i][j]);
        }
        __syncthreads();
    }

    #pragma unroll
    for (int i = 0; i < 4; i++) {
        float4 o = make_float4(acc[i][0], acc[i][1], acc[i][2], acc[i][3]);
        *(float4*)&C[(size_t)(m0 + ty * 4 + i) * DHh + tx * 4] = o;
    }
}

__global__ void qkv_reduce()
{
    const int sel = blockIdx.y;
    const int i = blockIdx.x * 256 + threadIdx.x;
    float4 a = ((const float4*)&g_part[sel][0][0])[i];
    float4 b = ((const float4*)&g_part[sel][1][0])[i];
    float4 c = ((const float4*)&g_part[sel][2][0])[i];
    float4 d = ((const float4*)&g_part[sel][3][0])[i];
    float4 o;
    o.x = (a.x + b.x) + (c.x + d.x);
    o.y = (a.y + b.y) + (c.y + d.y);
    o.z = (a.z + b.z) + (c.z + d.z);
    o.w = (a.w + b.w) + (c.w + d.w);
    float* out = (sel == 0 ? g_q : sel == 1 ? g_k : g_v);
    ((float4*)out)[i] = o;
}

// ---------------- attention, window-split halves, 8 tokens/block ----------------
// grid (S/8, 2). 8 warps, 1 query/warp. K rows staged: 128 + 7 + 1 = 136.
#define HT   8
#define KH   136
#define KHP  68
#define PP2  140

#define ASM_K  0
#define ASM_P  (KH * KHP)            // 9248 (Rs overlay needs 8*8*64=4096 <= this)
#define ASM_Q  (ASM_P + HT * PP2)    // 9248 + 1120 = 10368
#define ASM_T  (ASM_Q + HT * DHh)    // 10880 floats = 43520 B

__global__ __launch_bounds__(256) void attn_half()
{
    extern __shared__ float sm[];
    float* Ks = sm + ASM_K;
    float* Ps = sm + ASM_P;
    float* Qs = sm + ASM_Q;
    float* Rs = sm + ASM_K;          // AV partials overlay Ks (4096 <= 9248)

    const int t    = threadIdx.x;    // 256
    const int w    = t >> 5;         // 0..7
    const int lane = t & 31;
    const int j0   = blockIdx.x * HT;
    const int hf   = blockIdx.y;
    const int kstart = j0 - CWw + 128 * hf;

    // stage K (136 rows) + Q (8 x 64)
    for (int f = t; f < KH * 16; f += 256) {
        int kk = f >> 4, d4 = f & 15;
        int gk = kstart + kk;
        float4 kv = make_float4(0.f, 0.f, 0.f, 0.f);
        if (gk >= 0 && gk < Sq) kv = ((const float4*)&g_k[(size_t)gk * DHh])[d4];
        *(float4*)&Ks[kk * KHP + d4 * 4] = kv;
    }
    if (t < HT * 16) {
        int q = t >> 4, d4 = t & 15;
        ((float4*)&Qs[q * DHh])[d4] = ((const float4*)&g_q[(size_t)(j0 + q) * DHh])[d4];
    }
    __syncthreads();

    // scores: warp w owns query q = w; lane covers kk = lane + 32jj (jj<5)
    {
        const int q = w;
        float a[5] = {};
        #pragma unroll
        for (int d4 = 0; d4 < 16; d4++) {
            float4 qa = *(const float4*)&Qs[q * DHh + d4 * 4];
            #pragma unroll
            for (int jj = 0; jj < 5; jj++) {
                int kk = lane + 32 * jj;
                int kks = kk < KH - 1 ? kk : KH - 1;   // clamp (masked below)
                const float4 kv = *(const float4*)&Ks[kks * KHP + d4 * 4];
                a[jj] = fmaf(kv.x, qa.x, fmaf(kv.y, qa.y, fmaf(kv.z, qa.z, fmaf(kv.w, qa.w, a[jj]))));
            }
        }
        float mx = -1e30f;
        #pragma unroll
        for (int jj = 0; jj < 5; jj++) {
            int kk = lane + 32 * jj;
            int gk = kstart + kk;
            bool ok = (gk >= 0) && (gk < Sq) && (kk >= q) && (kk < q + 128);
            a[jj] = ok ? a[jj] * 0.125f : -1e30f;
            mx = fmaxf(mx, a[jj]);
        }
        #pragma unroll
        for (int o = 16; o; o >>= 1) mx = fmaxf(mx, __shfl_xor_sync(0xffffffffu, mx, o));
        float s = 0.f;
        #pragma unroll
        for (int jj = 0; jj < 5; jj++) {
            int kk = lane + 32 * jj;
            float e = __expf(a[jj] - mx);
            s += e;
            if (kk < KH) Ps[q * PP2 + kk] = e;
        }
        #pragma unroll
        for (int o = 16; o; o >>= 1) s += __shfl_xor_sync(0xffffffffu, s, o);
        if (lane == 0) {
            g_pm[hf][j0 + q] = mx;
            g_ps[hf][j0 + q] = s;
        }
    }
    __syncthreads();   // Ps done; Ks dead

    // AV (unnormalized): warp w owns keys [17w, 17w+17); V from L2
    {
        const int qh = (lane >> 4) * 4;   // half-warp covers queries qh..qh+3
        const int d4 = lane & 15;
        float4 r[4] = {};
        #pragma unroll
        for (int i = 0; i < 17; i++) {
            int kk = w * 17 + i;
            int gk = kstart + kk;
            float4 v4 = make_float4(0.f, 0.f, 0.f, 0.f);
            if (gk >= 0 && gk < Sq)
                v4 = ((const float4*)&g_v[(size_t)gk * DHh])[d4];
            #pragma unroll
            for (int qi = 0; qi < 4; qi++) {
                float p = Ps[(qh + qi) * PP2 + kk];
                r[qi].x = fmaf(p, v4.x, r[qi].x);
                r[qi].y = fmaf(p, v4.y, r[qi].y);
                r[qi].z = fmaf(p, v4.z, r[qi].z);
                r[qi].w = fmaf(p, v4.w, r[qi].w);
            }
        }
        #pragma unroll
        for (int qi = 0; qi < 4; qi++)
            *(float4*)&Rs[(w * HT + qh + qi) * DHh + d4 * 4] = r[qi];
    }
    __syncthreads();

    // reduce 8 warp-partials -> g_pv (8 x 64 = 512 outputs)
    #pragma unroll
    for (int ii = 0; ii < 2; ii++) {
        int idx = t + 256 * ii;          // 0..511
        int q = idx >> 6, d = idx & 63;
        float s = 0.f;
        #pragma unroll
        for (int ww = 0; ww < 8; ww++) s += Rs[(ww * HT + q) * DHh + d];
        g_pv[hf][(size_t)(j0 + q) * DHh + d] = s;
    }
}

// ---------------- up-projection, n-split halves ----------------------------------
// grid (S/16, 2). Block handles 16 tokens x 256 n-cols (W half in smem, no transpose).
// Emits y (complete for its n-half) + per-token partial sums(y), sums(y^2).
#define WH  256
#define WPn 68

__global__ __launch_bounds__(256) void up_half(const float* __restrict__ Wvu, int h)
{
    extern __shared__ float sm[];
    float* Ws = sm;                  // [256][68]
    float* As = sm + WH * WPn;       // [16][64]

    const int t    = threadIdx.x;    // 256
    const int w    = t >> 5;
    const int lane = t & 31;
    const int m0   = blockIdx.x * 16;
    const int nh   = blockIdx.y;
    const float* Wg = Wvu + (size_t)h * Dd * DHh + (size_t)nh * WH * DHh;

    // stage W half (256 x 64), straight float4 copy
    #pragma unroll
    for (int r = 0; r < 16; r++) {
        int f = t + r * 256;
        int row = f >> 4, k4 = f & 15;
        *(float4*)&Ws[row * WPn + k4 * 4] =
            *(const float4*)&Wg[(size_t)row * DHh + k4 * 4];
    }

    // combine 2 softmax halves -> As (16 x 64)
    #pragma unroll
    for (int ii = 0; ii < 4; ii++) {
        int idx = t + 256 * ii;          // 0..1023
        int q = idx >> 6, d = idx & 63;
        int m = m0 + q;
        float ma = g_pm[0][m], mb = g_pm[1][m];
        float M  = fmaxf(ma, mb);
        float ca = __expf(ma - M), cb = __expf(mb - M);
        float denom = ca * g_ps[0][m] + cb * g_ps[1][m];
        float pv = ca * g_pv[0][(size_t)m * DHh + d] + cb * g_pv[1][(size_t)m * DHh + d];
        As[q * DHh + d] = pv / denom;
    }
    __syncthreads();

    // GEMM: warp owns tokens 2w, 2w+1; lane owns 8 local n-cols (lane + 32j)
    const int tok0 = 2 * w, tok1 = 2 * w + 1;
    float acc0[8] = {}, acc1[8] = {};
    #pragma unroll
    for (int k4 = 0; k4 < 16; k4++) {
        float4 a0 = *(const float4*)&As[tok0 * DHh + k4 * 4];
        float4 a1 = *(const float4*)&As[tok1 * DHh + k4 * 4];
        #pragma unroll
        for (int j = 0; j < 8; j++) {
            float4 wv = *(const float4*)&Ws[(lane + 32 * j) * WPn + k4 * 4];
            acc0[j] = fmaf(a0.x, wv.x, fmaf(a0.y, wv.y, fmaf(a0.z, wv.z, fmaf(a0.w, wv.w, acc0[j]))));
            acc1[j] = fmaf(a1.x, wv.x, fmaf(a1.y, wv.y, fmaf(a1.z, wv.z, fmaf(a1.w, wv.w, acc1[j]))));
        }
    }

    // y = acc + cur; write y; warp-reduce per-token sums over this n-half
    #pragma unroll
    for (int tk = 0; tk < 2; tk++) {
        const int m = m0 + 2 * w + tk;
        const float* accp = tk == 0 ? acc0 : acc1;
        float s1 = 0.f, s2 = 0.f;
        #pragma unroll
        for (int j = 0; j < 8; j++) {
            int n = nh * WH + lane + 32 * j;
            float y = accp[j] + g_cur[(size_t)m * Dd + n];
            g_y[(size_t)m * Dd + n] = y;
            s1 += y;
            s2 = fmaf(y, y, s2);
        }
        #pragma unroll
        for (int o = 16; o; o >>= 1) {
            s1 += __shfl_xor_sync(0xffffffffu, s1, o);
            s2 += __shfl_xor_sync(0xffffffffu, s2, o);
        }
        if (lane == 0) {
            g_s1[nh][m] = s1;
            g_s2[nh][m] = s2;
        }
    }
}

// ---------------- final renorm: uses m2 == 1 identity ----------------------------
// new_cur = cur + (y/m1 - 1)/sd + 1,  sd^2 = (sum(y^2)/m1^2 - 512)/511
__global__ __launch_bounds__(128) void renorm_fin(int last, float* __restrict__ out)
{
    const int j = blockIdx.x;
    const int t = threadIdx.x;       // 128 threads x 1 float4

    float s1 = g_s1[0][j] + g_s1[1][j];
    float q2 = g_s2[0][j] + g_s2[1][j];
    float m1 = s1 * (1.f / 512.f);
    float inv_m1 = 1.f / m1;
    float sd2 = (q2 * inv_m1 * inv_m1 - 512.f) * (1.f / 511.f);
    float inv_sd = rsqrtf(sd2);

    float4 y4 = ((const float4*)&g_y[(size_t)j * Dd])[t];
    float4 c4 = ((const float4*)&g_cur[(size_t)j * Dd])[t];
    float4 nv;
    nv.x = c4.x + (y4.x * inv_m1 - 1.f) * inv_sd + 1.f;
    nv.y = c4.y + (y4.y * inv_m1 - 1.f) * inv_sd + 1.f;
    nv.z = c4.z + (y4.z * inv_m1 - 1.f) * inv_sd + 1.f;
    nv.w = c4.w + (y4.w * inv_m1 - 1.f) * inv_sd + 1.f;
    ((float4*)&g_cur[(size_t)j * Dd])[t] = nv;
    if (last) {
        nv.x *= 0.125f; nv.y *= 0.125f; nv.z *= 0.125f; nv.w *= 0.125f;
        ((float4*)&out[(size_t)j * Dd])[t] = nv;
    }
}

// ---------------- launch ---------------------------------------------------------
extern "C" void kernel_launch(void* const* d_in, const int* in_sizes, int n_in,
                              void* d_out, int out_size)
{
    const float* x   = (const float*)d_in[0];
    const float* Wq  = (const float*)d_in[1];
    const float* Wk  = (const float*)d_in[2];
    const float* Wvd = (const float*)d_in[3];
    const float* Wvu = (const float*)d_in[4];
    float* out = (float*)d_out;

    const int attn_smem = ASM_T * 4;                      // 43520 B
    const int up_smem   = (WH * WPn + 16 * DHh) * 4;      // 73728 B
    cudaFuncSetAttribute(attn_half, cudaFuncAttributeMaxDynamicSharedMemorySize, attn_smem);
    cudaFuncSetAttribute(up_half, cudaFuncAttributeMaxDynamicSharedMemorySize, up_smem);

    init_kernel<<<(Sq * Dd / 4) / 256, 256>>>((const float4*)x);
    for (int h = 0; h < Hh; h++) {
        qkv_partial<<<dim3(Sq / 32, 3, NSPLIT), 128>>>(Wq, Wk, Wvd, h);
        qkv_reduce<<<dim3(Sq * DHh / 4 / 256, 3), 256>>>();
        attn_half<<<dim3(Sq / HT, 2), 256, attn_smem>>>();
        up_half<<<dim3(Sq / 16, 2), 256, up_smem>>>(Wvu, h);
        renorm_fin<<<Sq, 128>>>(h == Hh - 1 ? 1 : 0, out);
    }
}

// round 13
// speedup vs baseline: 1.1633x; 1.1633x over previous
#include <cuda_runtime.h>
#include <math.h>

#define Sq  2048
#define Dd  512
#define Hh  8
#define DHh 64
#define CWw 128
#define NSPLIT 4
#define KSPL (Dd / NSPLIT)    // 128

// ---------------- scratch (device globals) -------------------------------------
__device__ float g_cur[Sq * Dd];
__device__ float g_q[Sq * DHh];
__device__ float g_k[Sq * DHh];
__device__ float g_v[Sq * DHh];
__device__ float g_part[3][NSPLIT][Sq * DHh];
__device__ float g_pm[2][Sq];            // partial softmax max
__device__ float g_ps[2][Sq];            // partial softmax sum(exp)
__device__ float g_pv[2][Sq * DHh];      // partial sum(exp * V)
__device__ int   g_cnt[3 * 64];          // split-K completion counters

// ---------------- init: cur = x, counters = 0 -----------------------------------
__global__ void init_kernel(const float4* __restrict__ x) {
    int i = blockIdx.x * blockDim.x + threadIdx.x;
    ((float4*)g_cur)[i] = x[i];
    if (i < 3 * 64) g_cnt[i] = 0;
}

// ---------------- qkv split-K partial GEMM + fused last-block reduce ------------
__global__ __launch_bounds__(128) void qkv_partial(const float* __restrict__ Wq,
                                                   const float* __restrict__ Wk,
                                                   const float* __restrict__ Wvd, int h)
{
    __shared__ float Xs[32][36];
    __shared__ float Ws[32][68];
    __shared__ int   s_done;

    const int sel = blockIdx.y;
    const int sp  = blockIdx.z;
    const float* B = (sel == 0 ? Wq : sel == 1 ? Wk : Wvd) + (size_t)h * DHh * Dd;
    float* C = &g_part[sel][sp][0];
    const int m0 = blockIdx.x * 32;
    const int kb = sp * KSPL;

    const int t  = threadIdx.x;
    const int tx = t & 15;
    const int ty = t >> 4;

    float acc[4][4] = {};

    for (int k0 = kb; k0 < kb + KSPL; k0 += 32) {
        #pragma unroll
        for (int r = 0; r < 2; r++) {
            int f = t + r * 128;
            int m = f >> 3, kv = f & 7;
            float4 va = *(const float4*)&g_cur[(size_t)(m0 + m) * Dd + k0 + kv * 4];
            Xs[kv * 4 + 0][m] = va.x;
            Xs[kv * 4 + 1][m] = va.y;
            Xs[kv * 4 + 2][m] = va.z;
            Xs[kv * 4 + 3][m] = va.w;
        }
        #pragma unroll
        for (int r = 0; r < 4; r++) {
            int f = t + r * 128;
            int n = f >> 3, kv = f & 7;
            float4 vb = *(const float4*)&B[(size_t)n * Dd + k0 + kv * 4];
            Ws[kv * 4 + 0][n] = vb.x;
            Ws[kv * 4 + 1][n] = vb.y;
            Ws[kv * 4 + 2][n] = vb.z;
            Ws[kv * 4 + 3][n] = vb.w;
        }
        __syncthreads();

        #pragma unroll
        for (int k = 0; k < 32; k++) {
            float4 a4 = *(const float4*)&Xs[k][ty * 4];
            float4 b4 = *(const float4*)&Ws[k][tx * 4];
            float a[4] = {a4.x, a4.y, a4.z, a4.w};
            float b[4] = {b4.x, b4.y, b4.z, b4.w};
            #pragma unroll
            for (int i = 0; i < 4; i++)
                #pragma unroll
                for (int j = 0; j < 4; j++)
                    acc[i][j] = fmaf(a[i], b[j], acc[i][j]);
        }
        __syncthreads();
    }

    #pragma unroll
    for (int i = 0; i < 4; i++) {
        float4 o = make_float4(acc[i][0], acc[i][1], acc[i][2], acc[i][3]);
        *(float4*)&C[(size_t)(m0 + ty * 4 + i) * DHh + tx * 4] = o;
    }

    // ---- last arriving split-block reduces the 4 partials (deterministic order)
    __threadfence();
    if (t == 0) s_done = atomicAdd(&g_cnt[sel * 64 + blockIdx.x], 1);
    __syncthreads();
    if ((s_done & 3) == 3) {
        float* outp = (sel == 0 ? g_q : sel == 1 ? g_k : g_v);
        #pragma unroll
        for (int r = 0; r < 4; r++) {
            int i = t + r * 128;              // 512 float4 outputs
            int m = i >> 4, n4 = i & 15;
            size_t off = (size_t)(m0 + m) * DHh + n4 * 4;
            float4 a = *(const float4*)&g_part[sel][0][off];
            float4 b = *(const float4*)&g_part[sel][1][off];
            float4 c = *(const float4*)&g_part[sel][2][off];
            float4 d = *(const float4*)&g_part[sel][3][off];
            float4 o;
            o.x = (a.x + b.x) + (c.x + d.x);
            o.y = (a.y + b.y) + (c.y + d.y);
            o.z = (a.z + b.z) + (c.z + d.z);
            o.w = (a.w + b.w) + (c.w + d.w);
            *(float4*)&outp[off] = o;
        }
    }
}

// ---------------- attention, window-split halves (R11 proven) -------------------
#define HT   16
#define KH   144
#define KHP  68
#define PP2  148

#define ASM_K  0
#define ASM_P  (KH * KHP)            // 9792
#define ASM_Q  (ASM_P + HT * PP2)    // +2368
#define ASM_T  (ASM_Q + HT * DHh)    // 13184 floats = 52736 B

__global__ __launch_bounds__(256) void attn_half()
{
    extern __shared__ float sm[];
    float* Ks = sm + ASM_K;
    float* Ps = sm + ASM_P;
    float* Qs = sm + ASM_Q;
    float* Rs = sm + ASM_K;          // AV partials overlay Ks (8192 <= 9792)

    const int t    = threadIdx.x;    // 256
    const int w    = t >> 5;
    const int lane = t & 31;
    const int j0   = blockIdx.x * HT;
    const int hf   = blockIdx.y;
    const int kstart = j0 - CWw + 128 * hf;

    for (int f = t; f < KH * 16; f += 256) {
        int kk = f >> 4, d4 = f & 15;
        int gk = kstart + kk;
        float4 kv = make_float4(0.f, 0.f, 0.f, 0.f);
        if (gk >= 0 && gk < Sq) kv = ((const float4*)&g_k[(size_t)gk * DHh])[d4];
        *(float4*)&Ks[kk * KHP + d4 * 4] = kv;
    }
    {
        int q = t >> 4, d4 = t & 15;
        ((float4*)&Qs[q * DHh])[d4] = ((const float4*)&g_q[(size_t)(j0 + q) * DHh])[d4];
    }
    __syncthreads();

    const int q0 = 2 * w, q1 = 2 * w + 1;
    {
        float a0[5] = {}, a1[5] = {};
        #pragma unroll
        for (int d4 = 0; d4 < 16; d4++) {
            float4 qa = *(const float4*)&Qs[q0 * DHh + d4 * 4];
            float4 qb = *(const float4*)&Qs[q1 * DHh + d4 * 4];
            #pragma unroll
            for (int jj = 0; jj < 5; jj++) {
                int kk = lane + 32 * jj;
                int kks = kk < KH - 1 ? kk : KH - 1;
                const float4 kv = *(const float4*)&Ks[kks * KHP + d4 * 4];
                a0[jj] = fmaf(kv.x, qa.x, fmaf(kv.y, qa.y, fmaf(kv.z, qa.z, fmaf(kv.w, qa.w, a0[jj]))));
                a1[jj] = fmaf(kv.x, qb.x, fmaf(kv.y, qb.y, fmaf(kv.z, qb.z, fmaf(kv.w, qb.w, a1[jj]))));
            }
        }
        float m0 = -1e30f, m1 = -1e30f;
        #pragma unroll
        for (int jj = 0; jj < 5; jj++) {
            int kk = lane + 32 * jj;
            int gk = kstart + kk;
            bool gok = (gk >= 0) && (gk < Sq);
            bool v0 = gok && (kk >= q0) && (kk < q0 + 128);
            bool v1 = gok && (kk >= q1) && (kk < q1 + 128);
            a0[jj] = v0 ? a0[jj] * 0.125f : -1e30f;
            a1[jj] = v1 ? a1[jj] * 0.125f : -1e30f;
            m0 = fmaxf(m0, a0[jj]);
            m1 = fmaxf(m1, a1[jj]);
        }
        #pragma unroll
        for (int o = 16; o; o >>= 1) {
            m0 = fmaxf(m0, __shfl_xor_sync(0xffffffffu, m0, o));
            m1 = fmaxf(m1, __shfl_xor_sync(0xffffffffu, m1, o));
        }
        float s0 = 0.f, s1 = 0.f;
        #pragma unroll
        for (int jj = 0; jj < 5; jj++) {
            int kk = lane + 32 * jj;
            float e0 = __expf(a0[jj] - m0);
            float e1 = __expf(a1[jj] - m1);
            s0 += e0;
            s1 += e1;
            if (kk < KH) {
                Ps[q0 * PP2 + kk] = e0;
                Ps[q1 * PP2 + kk] = e1;
            }
        }
        #pragma unroll
        for (int o = 16; o; o >>= 1) {
            s0 += __shfl_xor_sync(0xffffffffu, s0, o);
            s1 += __shfl_xor_sync(0xffffffffu, s1, o);
        }
        if (lane == 0) {
            g_pm[hf][j0 + q0] = m0;
            g_pm[hf][j0 + q1] = m1;
            g_ps[hf][j0 + q0] = s0;
            g_ps[hf][j0 + q1] = s1;
        }
    }
    __syncthreads();

    // AV: warp w owns keys [18w, 18w+18); pairs of keys, float2 P loads
    {
        const int qh = (lane >> 4) * 8;
        const int d4 = lane & 15;
        float4 r[8] = {};
        #pragma unroll
        for (int i = 0; i < 18; i += 2) {
            int kk = w * 18 + i;          // even (18w even, i even)
            int gka = kstart + kk;
            int gkb = gka + 1;
            float4 va = make_float4(0.f, 0.f, 0.f, 0.f);
            float4 vb = va;
            if (gka >= 0 && gka < Sq) va = ((const float4*)&g_v[(size_t)gka * DHh])[d4];
            if (gkb >= 0 && gkb < Sq) vb = ((const float4*)&g_v[(size_t)gkb * DHh])[d4];
            #pragma unroll
            for (int qi = 0; qi < 8; qi++) {
                float2 p = *(const float2*)&Ps[(qh + qi) * PP2 + kk];
                r[qi].x = fmaf(p.x, va.x, fmaf(p.y, vb.x, r[qi].x));
                r[qi].y = fmaf(p.x, va.y, fmaf(p.y, vb.y, r[qi].y));
                r[qi].z = fmaf(p.x, va.z, fmaf(p.y, vb.z, r[qi].z));
                r[qi].w = fmaf(p.x, va.w, fmaf(p.y, vb.w, r[qi].w));
            }
        }
        #pragma unroll
        for (int qi = 0; qi < 8; qi++)
            *(float4*)&Rs[(w * HT + qh + qi) * DHh + d4 * 4] = r[qi];
    }
    __syncthreads();

    #pragma unroll
    for (int ii = 0; ii < 4; ii++) {
        int idx = t + 256 * ii;
        int q = idx >> 6, d = idx & 63;
        float s = 0.f;
        #pragma unroll
        for (int ww = 0; ww < 8; ww++) s += Rs[(ww * HT + q) * DHh + d];
        g_pv[hf][(size_t)(j0 + q) * DHh + d] = s;
    }
}

// ---------------- fused combine + up-projection + residual + renorm -------------
// R11 proven: 16 tokens/block, 256 threads, W in natural [n][k] layout.
#define WPn 68

__global__ __launch_bounds__(256) void upnorm_kernel(const float* __restrict__ Wvu,
                                                     int h, int last,
                                                     float* __restrict__ out)
{
    extern __shared__ float sm[];
    float* Ws = sm;                  // [512][68]
    float* As = sm + Dd * WPn;       // [16][64]

    const int t    = threadIdx.x;    // 256
    const int w    = t >> 5;
    const int lane = t & 31;
    const int m0   = blockIdx.x * 16;
    const float* Wg = Wvu + (size_t)h * Dd * DHh;

    #pragma unroll
    for (int r = 0; r < 32; r++) {
        int f = t + r * 256;
        int row = f >> 4, k4 = f & 15;
        *(float4*)&Ws[row * WPn + k4 * 4] =
            *(const float4*)&Wg[(size_t)row * DHh + k4 * 4];
    }

    #pragma unroll
    for (int ii = 0; ii < 4; ii++) {
        int idx = t + 256 * ii;          // 0..1023
        int q = idx >> 6, d = idx & 63;
        int m = m0 + q;
        float ma = g_pm[0][m], mb = g_pm[1][m];
        float M  = fmaxf(ma, mb);
        float ca = __expf(ma - M), cb = __expf(mb - M);
        float denom = ca * g_ps[0][m] + cb * g_ps[1][m];
        float pv = ca * g_pv[0][(size_t)m * DHh + d] + cb * g_pv[1][(size_t)m * DHh + d];
        As[q * DHh + d] = pv / denom;
    }
    __syncthreads();

    const int tok0 = 2 * w, tok1 = 2 * w + 1;
    float acc0[16] = {}, acc1[16] = {};
    #pragma unroll
    for (int k4 = 0; k4 < 16; k4++) {
        float4 a0 = *(const float4*)&As[tok0 * DHh + k4 * 4];
        float4 a1 = *(const float4*)&As[tok1 * DHh + k4 * 4];
        #pragma unroll
        for (int j = 0; j < 16; j++) {
            float4 wv = *(const float4*)&Ws[(lane + 32 * j) * WPn + k4 * 4];
            acc0[j] = fmaf(a0.x, wv.x, fmaf(a0.y, wv.y, fmaf(a0.z, wv.z, fmaf(a0.w, wv.w, acc0[j]))));
            acc1[j] = fmaf(a1.x, wv.x, fmaf(a1.y, wv.y, fmaf(a1.z, wv.z, fmaf(a1.w, wv.w, acc1[j]))));
        }
    }

    #pragma unroll
    for (int tk = 0; tk < 2; tk++) {
        const int m = m0 + 2 * w + tk;
        const float* accp = tk == 0 ? acc0 : acc1;
        float cres[16], y[16];
        float s = 0.f;
        #pragma unroll
        for (int j = 0; j < 16; j++) {
            int n = lane + 32 * j;
            cres[j] = g_cur[(size_t)m * Dd + n];
            y[j] = accp[j] + cres[j];
            s += y[j];
        }
        #pragma unroll
        for (int o = 16; o; o >>= 1) s += __shfl_xor_sync(0xffffffffu, s, o);
        float im = 512.f / s;                       // 1/m1
        s = 0.f;
        #pragma unroll
        for (int j = 0; j < 16; j++) { y[j] *= im; s += y[j]; }
        #pragma unroll
        for (int o = 16; o; o >>= 1) s += __shfl_xor_sync(0xffffffffu, s, o);
        float m2 = s * (1.f / 512.f);
        float v = 0.f;
        #pragma unroll
        for (int j = 0; j < 16; j++) { y[j] -= m2; v += y[j] * y[j]; }
        #pragma unroll
        for (int o = 16; o; o >>= 1) v += __shfl_xor_sync(0xffffffffu, v, o);
        float is = rsqrtf(v * (1.f / 511.f));

        #pragma unroll
        for (int j = 0; j < 16; j++) {
            int n = lane + 32 * j;
            float nv = cres[j] + y[j] * is + m2;
            g_cur[(size_t)m * Dd + n] = nv;
            if (last) out[(size_t)m * Dd + n] = nv * 0.125f;
        }
    }
}

// ---------------- launch ---------------------------------------------------------
extern "C" void kernel_launch(void* const* d_in, const int* in_sizes, int n_in,
                              void* d_out, int out_size)
{
    const float* x   = (const float*)d_in[0];
    const float* Wq  = (const float*)d_in[1];
    const float* Wk  = (const float*)d_in[2];
    const float* Wvd = (const float*)d_in[3];
    const float* Wvu = (const float*)d_in[4];
    float* out = (float*)d_out;

    const int attn_smem = ASM_T * 4;                      // 52736 B
    const int up_smem   = (Dd * WPn + 16 * DHh) * 4;      // 143360 B
    cudaFuncSetAttribute(attn_half, cudaFuncAttributeMaxDynamicSharedMemorySize, attn_smem);
    cudaFuncSetAttribute(upnorm_kernel, cudaFuncAttributeMaxDynamicSharedMemorySize, up_smem);

    init_kernel<<<(Sq * Dd / 4) / 256, 256>>>((const float4*)x);
    for (int h = 0; h < Hh; h++) {
        qkv_partial<<<dim3(Sq / 32, 3, NSPLIT), 128>>>(Wq, Wk, Wvd, h);
        attn_half<<<dim3(Sq / HT, 2), 256, attn_smem>>>();
        upnorm_kernel<<<Sq / 16, 256, up_smem>>>(Wvu, h, h == Hh - 1 ? 1 : 0, out);
    }
}

// round 14
// speedup vs baseline: 1.2483x; 1.0731x over previous
#include <cuda_runtime.h>
#include <math.h>

#define Sq  2048
#define Dd  512
#define Hh  8
#define DHh 64
#define CWw 128
#define NSPLIT 4
#define KSPL (Dd / NSPLIT)    // 128

// ---------------- scratch (device globals) -------------------------------------
__device__ float g_cur[Sq * Dd];
__device__ float g_q[Sq * DHh];
__device__ float g_k[Sq * DHh];
__device__ float g_v[Sq * DHh];
__device__ float g_part[3][NSPLIT][Sq * DHh];
__device__ float g_pm[2][Sq];            // partial softmax max
__device__ float g_ps[2][Sq];            // partial softmax sum(exp)
__device__ float g_pv[2][Sq * DHh];      // partial sum(exp * V)

// ---------------- init: cur = x -------------------------------------------------
__global__ void init_kernel(const float4* __restrict__ x) {
    int i = blockIdx.x * blockDim.x + threadIdx.x;
    ((float4*)g_cur)[i] = x[i];
}

// ---------------- qkv split-K partial GEMM (R11 proven) -------------------------
__global__ __launch_bounds__(128) void qkv_partial(const float* __restrict__ Wq,
                                                   const float* __restrict__ Wk,
                                                   const float* __restrict__ Wvd, int h)
{
    __shared__ float Xs[32][36];
    __shared__ float Ws[32][68];

    const int sel = blockIdx.y;
    const int sp  = blockIdx.z;
    const float* B = (sel == 0 ? Wq : sel == 1 ? Wk : Wvd) + (size_t)h * DHh * Dd;
    float* C = &g_part[sel][sp][0];
    const int m0 = blockIdx.x * 32;
    const int kb = sp * KSPL;

    const int t  = threadIdx.x;
    const int tx = t & 15;
    const int ty = t >> 4;

    float acc[4][4] = {};

    for (int k0 = kb; k0 < kb + KSPL; k0 += 32) {
        #pragma unroll
        for (int r = 0; r < 2; r++) {
            int f = t + r * 128;
            int m = f >> 3, kv = f & 7;
            float4 va = *(const float4*)&g_cur[(size_t)(m0 + m) * Dd + k0 + kv * 4];
            Xs[kv * 4 + 0][m] = va.x;
            Xs[kv * 4 + 1][m] = va.y;
            Xs[kv * 4 + 2][m] = va.z;
            Xs[kv * 4 + 3][m] = va.w;
        }
        #pragma unroll
        for (int r = 0; r < 4; r++) {
            int f = t + r * 128;
            int n = f >> 3, kv = f & 7;
            float4 vb = *(const float4*)&B[(size_t)n * Dd + k0 + kv * 4];
            Ws[kv * 4 + 0][n] = vb.x;
            Ws[kv * 4 + 1][n] = vb.y;
            Ws[kv * 4 + 2][n] = vb.z;
            Ws[kv * 4 + 3][n] = vb.w;
        }
        __syncthreads();

        #pragma unroll
        for (int k = 0; k < 32; k++) {
            float4 a4 = *(const float4*)&Xs[k][ty * 4];
            float4 b4 = *(const float4*)&Ws[k][tx * 4];
            float a[4] = {a4.x, a4.y, a4.z, a4.w};
            float b[4] = {b4.x, b4.y, b4.z, b4.w};
            #pragma unroll
            for (int i = 0; i < 4; i++)
                #pragma unroll
                for (int j = 0; j < 4; j++)
                    acc[i][j] = fmaf(a[i], b[j], acc[i][j]);
        }
        __syncthreads();
    }

    #pragma unroll
    for (int i = 0; i < 4; i++) {
        float4 o = make_float4(acc[i][0], acc[i][1], acc[i][2], acc[i][3]);
        *(float4*)&C[(size_t)(m0 + ty * 4 + i) * DHh + tx * 4] = o;
    }
}

__global__ void qkv_reduce()
{
    const int sel = blockIdx.y;
    const int i = blockIdx.x * 256 + threadIdx.x;
    float4 a = ((const float4*)&g_part[sel][0][0])[i];
    float4 b = ((const float4*)&g_part[sel][1][0])[i];
    float4 c = ((const float4*)&g_part[sel][2][0])[i];
    float4 d = ((const float4*)&g_part[sel][3][0])[i];
    float4 o;
    o.x = (a.x + b.x) + (c.x + d.x);
    o.y = (a.y + b.y) + (c.y + d.y);
    o.z = (a.z + b.z) + (c.z + d.z);
    o.w = (a.w + b.w) + (c.w + d.w);
    float* out = (sel == 0 ? g_q : sel == 1 ? g_k : g_v);
    ((float4*)out)[i] = o;
}

// ---------------- attention, window-split halves (R11 proven, verbatim) ---------
#define HT   16
#define KH   144
#define KHP  68
#define PP2  148

#define ASM_K  0
#define ASM_P  (KH * KHP)            // 9792
#define ASM_Q  (ASM_P + HT * PP2)    // +2368
#define ASM_T  (ASM_Q + HT * DHh)    // 13184 floats = 52736 B

__global__ __launch_bounds__(256) void attn_half()
{
    extern __shared__ float sm[];
    float* Ks = sm + ASM_K;
    float* Ps = sm + ASM_P;
    float* Qs = sm + ASM_Q;
    float* Rs = sm + ASM_K;          // AV partials overlay Ks (8192 <= 9792)

    const int t    = threadIdx.x;    // 256
    const int w    = t >> 5;
    const int lane = t & 31;
    const int j0   = blockIdx.x * HT;
    const int hf   = blockIdx.y;
    const int kstart = j0 - CWw + 128 * hf;

    for (int f = t; f < KH * 16; f += 256) {
        int kk = f >> 4, d4 = f & 15;
        int gk = kstart + kk;
        float4 kv = make_float4(0.f, 0.f, 0.f, 0.f);
        if (gk >= 0 && gk < Sq) kv = ((const float4*)&g_k[(size_t)gk * DHh])[d4];
        *(float4*)&Ks[kk * KHP + d4 * 4] = kv;
    }
    {
        int q = t >> 4, d4 = t & 15;
        ((float4*)&Qs[q * DHh])[d4] = ((const float4*)&g_q[(size_t)(j0 + q) * DHh])[d4];
    }
    __syncthreads();

    const int q0 = 2 * w, q1 = 2 * w + 1;
    {
        float a0[5] = {}, a1[5] = {};
        #pragma unroll
        for (int d4 = 0; d4 < 16; d4++) {
            float4 qa = *(const float4*)&Qs[q0 * DHh + d4 * 4];
            float4 qb = *(const float4*)&Qs[q1 * DHh + d4 * 4];
            #pragma unroll
            for (int jj = 0; jj < 5; jj++) {
                int kk = lane + 32 * jj;
                int kks = kk < KH - 1 ? kk : KH - 1;
                const float4 kv = *(const float4*)&Ks[kks * KHP + d4 * 4];
                a0[jj] = fmaf(kv.x, qa.x, fmaf(kv.y, qa.y, fmaf(kv.z, qa.z, fmaf(kv.w, qa.w, a0[jj]))));
                a1[jj] = fmaf(kv.x, qb.x, fmaf(kv.y, qb.y, fmaf(kv.z, qb.z, fmaf(kv.w, qb.w, a1[jj]))));
            }
        }
        float m0 = -1e30f, m1 = -1e30f;
        #pragma unroll
        for (int jj = 0; jj < 5; jj++) {
            int kk = lane + 32 * jj;
            int gk = kstart + kk;
            bool gok = (gk >= 0) && (gk < Sq);
            bool v0 = gok && (kk >= q0) && (kk < q0 + 128);
            bool v1 = gok && (kk >= q1) && (kk < q1 + 128);
            a0[jj] = v0 ? a0[jj] * 0.125f : -1e30f;
            a1[jj] = v1 ? a1[jj] * 0.125f : -1e30f;
            m0 = fmaxf(m0, a0[jj]);
            m1 = fmaxf(m1, a1[jj]);
        }
        #pragma unroll
        for (int o = 16; o; o >>= 1) {
            m0 = fmaxf(m0, __shfl_xor_sync(0xffffffffu, m0, o));
            m1 = fmaxf(m1, __shfl_xor_sync(0xffffffffu, m1, o));
        }
        float s0 = 0.f, s1 = 0.f;
        #pragma unroll
        for (int jj = 0; jj < 5; jj++) {
            int kk = lane + 32 * jj;
            float e0 = __expf(a0[jj] - m0);
            float e1 = __expf(a1[jj] - m1);
            s0 += e0;
            s1 += e1;
            if (kk < KH) {
                Ps[q0 * PP2 + kk] = e0;
                Ps[q1 * PP2 + kk] = e1;
            }
        }
        #pragma unroll
        for (int o = 16; o; o >>= 1) {
            s0 += __shfl_xor_sync(0xffffffffu, s0, o);
            s1 += __shfl_xor_sync(0xffffffffu, s1, o);
        }
        if (lane == 0) {
            g_pm[hf][j0 + q0] = m0;
            g_pm[hf][j0 + q1] = m1;
            g_ps[hf][j0 + q0] = s0;
            g_ps[hf][j0 + q1] = s1;
        }
    }
    __syncthreads();

    {
        const int qh = (lane >> 4) * 8;
        const int d4 = lane & 15;
        float4 r[8] = {};
        #pragma unroll
        for (int i = 0; i < 18; i++) {
            int kk = w * 18 + i;
            int gk = kstart + kk;
            float4 v4 = make_float4(0.f, 0.f, 0.f, 0.f);
            if (gk >= 0 && gk < Sq)
                v4 = ((const float4*)&g_v[(size_t)gk * DHh])[d4];
            #pragma unroll
            for (int qi = 0; qi < 8; qi++) {
                float p = Ps[(qh + qi) * PP2 + kk];
                r[qi].x = fmaf(p, v4.x, r[qi].x);
                r[qi].y = fmaf(p, v4.y, r[qi].y);
                r[qi].z = fmaf(p, v4.z, r[qi].z);
                r[qi].w = fmaf(p, v4.w, r[qi].w);
            }
        }
        #pragma unroll
        for (int qi = 0; qi < 8; qi++)
            *(float4*)&Rs[(w * HT + qh + qi) * DHh + d4 * 4] = r[qi];
    }
    __syncthreads();

    #pragma unroll
    for (int ii = 0; ii < 4; ii++) {
        int idx = t + 256 * ii;
        int q = idx >> 6, d = idx & 63;
        float s = 0.f;
        #pragma unroll
        for (int ww = 0; ww < 8; ww++) s += Rs[(ww * HT + q) * DHh + d];
        g_pv[hf][(size_t)(j0 + q) * DHh + d] = s;
    }
}

// ---------------- fused combine + up-projection + residual + renorm -------------
// 16 tokens/block, 256 threads. Warp = 4 tokens x 256 cols (ch = w>>2 col-half).
// Renorm uses m2 == 1 identity (one reduction pass, validated R12).
#define WPn 68

__global__ __launch_bounds__(256) void upnorm_kernel(const float* __restrict__ Wvu,
                                                     int h, int last,
                                                     float* __restrict__ out)
{
    extern __shared__ float sm[];
    float* Ws   = sm;                     // [512][68]
    float* As   = sm + Dd * WPn;          // [16][64]
    float* RedS = As + 16 * DHh;          // [2][16]
    float* RedQ = RedS + 32;              // [2][16]

    const int t    = threadIdx.x;    // 256
    const int w    = t >> 5;
    const int lane = t & 31;
    const int wt   = w & 3;          // token group: tokens wt*4 .. wt*4+3
    const int ch   = w >> 2;         // column half: cols ch*256 .. ch*256+255
    const int m0   = blockIdx.x * 16;
    const float* Wg = Wvu + (size_t)h * Dd * DHh;

    // ---- stage W (512 x 64), straight float4 copy (no transpose)
    #pragma unroll
    for (int r = 0; r < 32; r++) {
        int f = t + r * 256;
        int row = f >> 4, k4 = f & 15;
        *(float4*)&Ws[row * WPn + k4 * 4] =
            *(const float4*)&Wg[(size_t)row * DHh + k4 * 4];
    }

    // ---- combine 2 softmax halves -> As (16 x 64)
    #pragma unroll
    for (int ii = 0; ii < 4; ii++) {
        int idx = t + 256 * ii;          // 0..1023
        int q = idx >> 6, d = idx & 63;
        int m = m0 + q;
        float ma = g_pm[0][m], mb = g_pm[1][m];
        float M  = fmaxf(ma, mb);
        float ca = __expf(ma - M), cb = __expf(mb - M);
        float denom = ca * g_ps[0][m] + cb * g_ps[1][m];
        float pv = ca * g_pv[0][(size_t)m * DHh + d] + cb * g_pv[1][(size_t)m * DHh + d];
        As[q * DHh + d] = pv / denom;
    }
    __syncthreads();

    // ---- GEMM: 4 tokens x 8 cols per lane (cols n = ch*256 + lane + 32j)
    float acc[4][8] = {};
    #pragma unroll
    for (int k4 = 0; k4 < 16; k4++) {
        float4 a[4];
        #pragma unroll
        for (int i = 0; i < 4; i++)
            a[i] = *(const float4*)&As[(wt * 4 + i) * DHh + k4 * 4];
        #pragma unroll
        for (int j = 0; j < 8; j++) {
            float4 wv = *(const float4*)&Ws[(ch * 256 + lane + 32 * j) * WPn + k4 * 4];
            #pragma unroll
            for (int i = 0; i < 4; i++)
                acc[i][j] = fmaf(a[i].x, wv.x, fmaf(a[i].y, wv.y,
                             fmaf(a[i].z, wv.z, fmaf(a[i].w, wv.w, acc[i][j]))));
        }
    }

    // ---- y = acc + cur; single-pass per-token sums (s, q2), cross-warp exchange
    float cres[4][8];
    #pragma unroll
    for (int i = 0; i < 4; i++) {
        const int m = m0 + wt * 4 + i;
        float s = 0.f, q2 = 0.f;
        #pragma unroll
        for (int j = 0; j < 8; j++) {
            int n = ch * 256 + lane + 32 * j;
            cres[i][j] = g_cur[(size_t)m * Dd + n];
            float y = acc[i][j] + cres[i][j];
            acc[i][j] = y;
            s += y;
            q2 = fmaf(y, y, q2);
        }
        #pragma unroll
        for (int o = 16; o; o >>= 1) {
            s  += __shfl_xor_sync(0xffffffffu, s, o);
            q2 += __shfl_xor_sync(0xffffffffu, q2, o);
        }
        if (lane == 0) {
            RedS[ch * 16 + wt * 4 + i] = s;
            RedQ[ch * 16 + wt * 4 + i] = q2;
        }
    }
    __syncthreads();

    // ---- renorm with m2 == 1:  new = cur + (y/m1 - 1)/sd + 1
    #pragma unroll
    for (int i = 0; i < 4; i++) {
        const int m = m0 + wt * 4 + i;
        float st = RedS[wt * 4 + i] + RedS[16 + wt * 4 + i];
        float qt = RedQ[wt * 4 + i] + RedQ[16 + wt * 4 + i];
        float m1 = st * (1.f / 512.f);
        float inv_m1 = 1.f / m1;
        float sd2 = (qt * inv_m1 * inv_m1 - 512.f) * (1.f / 511.f);
        float inv_sd = rsqrtf(sd2);

        #pragma unroll
        for (int j = 0; j < 8; j++) {
            int n = ch * 256 + lane + 32 * j;
            float nv = cres[i][j] + (acc[i][j] * inv_m1 - 1.f) * inv_sd + 1.f;
            g_cur[(size_t)m * Dd + n] = nv;
            if (last) out[(size_t)m * Dd + n] = nv * 0.125f;
        }
    }
}

// ---------------- launch ---------------------------------------------------------
extern "C" void kernel_launch(void* const* d_in, const int* in_sizes, int n_in,
                              void* d_out, int out_size)
{
    const float* x   = (const float*)d_in[0];
    const float* Wq  = (const float*)d_in[1];
    const float* Wk  = (const float*)d_in[2];
    const float* Wvd = (const float*)d_in[3];
    const float* Wvu = (const float*)d_in[4];
    float* out = (float*)d_out;

    const int attn_smem = ASM_T * 4;                           // 52736 B
    const int up_smem   = (Dd * WPn + 16 * DHh + 64) * 4;      // 143616 B
    cudaFuncSetAttribute(attn_half, cudaFuncAttributeMaxDynamicSharedMemorySize, attn_smem);
    cudaFuncSetAttribute(upnorm_kernel, cudaFuncAttributeMaxDynamicSharedMemorySize, up_smem);

    init_kernel<<<(Sq * Dd / 4) / 256, 256>>>((const float4*)x);
    for (int h = 0; h < Hh; h++) {
        qkv_partial<<<dim3(Sq / 32, 3, NSPLIT), 128>>>(Wq, Wk, Wvd, h);
        qkv_reduce<<<dim3(Sq * DHh / 4 / 256, 3), 256>>>();
        attn_half<<<dim3(Sq / HT, 2), 256, attn_smem>>>();
        upnorm_kernel<<<Sq / 16, 256, up_smem>>>(Wvu, h, h == Hh - 1 ? 1 : 0, out);
    }
}